// round 5
// baseline (speedup 1.0000x reference)
#include <cuda_runtime.h>

// ---------------------------------------------------------------------------
// TransducerJoint: logits[b,t,u,v] = tanh(enc_proj[b,t,:] + pred_proj[b,u,:]) @ W_out + b_out
// B=4, T=200, U=100, ENC=PRED=512, JOINT=640, VOCAB=1024
//
// Stage 1: E[800,640]  = enc_out[800,512]  @ W_enc  + b_enc
// Stage 2: P[400,640]  = pred_out[400,512] @ W_pred
// Stage 3: out[80000,1024] = tanh(E[bt]+P[b,u]) @ W_out + b_out (fused A-gen SGEMM)
// ---------------------------------------------------------------------------

#define B_DIM 4
#define T_DIM 200
#define U_DIM 100
#define ENC_DIM 512
#define JOINT_DIM 640
#define VOCAB 1024

// Static scratch for the small projections (allowed: __device__ globals).
__device__ float g_E[B_DIM * T_DIM * JOINT_DIM];   // [800, 640] ~2 MB
__device__ float g_P[B_DIM * U_DIM * JOINT_DIM];   // [400, 640] ~1 MB

// ---------------------------------------------------------------------------
// Projection SGEMM: C[M,640] = A[M,512] @ W[512,640] (+ bias)
// 64x64x16 tiling, 256 threads, 4x4 per-thread microtile. Tiny cost (<1%).
// DST=0 -> g_E, DST=1 -> g_P.
// ---------------------------------------------------------------------------
template <int DST, bool BIAS>
__global__ __launch_bounds__(256)
void proj_kernel(const float* __restrict__ A, const float* __restrict__ W,
                 const float* __restrict__ bias, int M)
{
    float* C = (DST == 0) ? g_E : g_P;
    const int BM = 64, BN = 64, BK = 16;
    __shared__ float As[BK][BM];
    __shared__ float Bs[BK][BN];

    const int t  = threadIdx.x;
    const int m0 = blockIdx.y * BM;
    const int n0 = blockIdx.x * BN;
    const int tx = t & 15;        // 0..15 -> N
    const int ty = t >> 4;        // 0..15 -> M

    const int arow = t >> 2;            // 0..63
    const int ak   = (t & 3) << 2;      // 0,4,8,12
    const int brow = t >> 4;            // 0..15
    const int bcol = (t & 15) << 2;     // 0..60

    float acc[4][4];
#pragma unroll
    for (int i = 0; i < 4; i++)
#pragma unroll
        for (int j = 0; j < 4; j++) acc[i][j] = 0.f;

    for (int k0 = 0; k0 < ENC_DIM; k0 += BK) {
        float4 av = make_float4(0.f, 0.f, 0.f, 0.f);
        if (m0 + arow < M)
            av = *(const float4*)(A + (size_t)(m0 + arow) * ENC_DIM + k0 + ak);
        As[ak + 0][arow] = av.x;
        As[ak + 1][arow] = av.y;
        As[ak + 2][arow] = av.z;
        As[ak + 3][arow] = av.w;

        *(float4*)&Bs[brow][bcol] =
            *(const float4*)(W + (size_t)(k0 + brow) * JOINT_DIM + n0 + bcol);
        __syncthreads();

#pragma unroll
        for (int k = 0; k < BK; k++) {
            float a[4], b[4];
#pragma unroll
            for (int i = 0; i < 4; i++) a[i] = As[k][ty * 4 + i];
#pragma unroll
            for (int j = 0; j < 4; j++) b[j] = Bs[k][tx * 4 + j];
#pragma unroll
            for (int i = 0; i < 4; i++)
#pragma unroll
                for (int j = 0; j < 4; j++)
                    acc[i][j] = fmaf(a[i], b[j], acc[i][j]);
        }
        __syncthreads();
    }

    float bv[4] = {0.f, 0.f, 0.f, 0.f};
    if (BIAS) {
        float4 b4 = *(const float4*)(bias + n0 + tx * 4);
        bv[0] = b4.x; bv[1] = b4.y; bv[2] = b4.z; bv[3] = b4.w;
    }
#pragma unroll
    for (int i = 0; i < 4; i++) {
        int row = m0 + ty * 4 + i;
        if (row < M) {
            float4 v;
            v.x = acc[i][0] + bv[0];
            v.y = acc[i][1] + bv[1];
            v.z = acc[i][2] + bv[2];
            v.w = acc[i][3] + bv[3];
            *(float4*)(C + (size_t)row * JOINT_DIM + n0 + tx * 4) = v;
        }
    }
}

// ---------------------------------------------------------------------------
// Main fused SGEMM: out[80000,1024] = tanh(E[bt] + P[b*100+u]) @ W_out + b_out
// 128x128x8 tiles, 256 threads, 8x8 microtile (split 4+4 fragments for
// conflict-free float4 LDS), double-buffered smem, A generated in loader.
// M=80000 and N=1024 divide evenly -> no bounds checks.
// ---------------------------------------------------------------------------
__global__ __launch_bounds__(256, 2)
void joint_kernel(const float* __restrict__ Wout, const float* __restrict__ bout,
                  float* __restrict__ out)
{
    const int BM = 128, BN = 128, BK = 8;
    __shared__ float As[2][BK][BM];
    __shared__ float Bs[2][BK][BN];

    const int t  = threadIdx.x;
    const int m0 = blockIdx.y * BM;
    const int n0 = blockIdx.x * BN;

    // ---- A producer indices: 128 rows x 8 k, one float4 of E + one of P each
    const int arow = t >> 1;            // 0..127
    const int ah   = (t & 1) * 4;       // 0 or 4 (k offset within BK)
    const int m  = m0 + arow;
    const int bt = m / U_DIM;           // b*T + t
    const int u  = m - bt * U_DIM;
    const int bb = bt / T_DIM;
    const float* Erow = g_E + (size_t)bt * JOINT_DIM + ah;
    const float* Prow = g_P + (size_t)(bb * U_DIM + u) * JOINT_DIM + ah;

    // ---- B producer indices: 8 rows x 128 cols, one float4 each
    const int brow = t >> 5;            // 0..7
    const int bcol = (t & 31) * 4;      // 0..124
    const float* Wp = Wout + (size_t)brow * VOCAB + n0 + bcol;

    // ---- compute thread mapping (split fragments)
    const int tx = t & 15;              // N fragment: [tx*4, 64+tx*4)
    const int ty = t >> 4;              // M fragment: [ty*4, 64+ty*4)

    float acc[8][8];
#pragma unroll
    for (int i = 0; i < 8; i++)
#pragma unroll
        for (int j = 0; j < 8; j++) acc[i][j] = 0.f;

    // ---- preload tile 0
    {
        float4 e = *(const float4*)(Erow);
        float4 p = *(const float4*)(Prow);
        As[0][ah + 0][arow] = tanhf(e.x + p.x);
        As[0][ah + 1][arow] = tanhf(e.y + p.y);
        As[0][ah + 2][arow] = tanhf(e.z + p.z);
        As[0][ah + 3][arow] = tanhf(e.w + p.w);
        *(float4*)&Bs[0][brow][bcol] = *(const float4*)(Wp);
    }
    __syncthreads();

    const int NT = JOINT_DIM / BK;      // 80
    for (int kt = 0; kt < NT; kt++) {
        const int cur = kt & 1;
        float4 e2, p2, w2;
        const bool more = (kt + 1 < NT);
        if (more) {
            const int koff = (kt + 1) * BK;
            e2 = *(const float4*)(Erow + koff);
            p2 = *(const float4*)(Prow + koff);
            w2 = *(const float4*)(Wp + (size_t)koff * VOCAB);
        }

#pragma unroll
        for (int k = 0; k < BK; k++) {
            float4 a0 = *(const float4*)&As[cur][k][ty * 4];
            float4 a1 = *(const float4*)&As[cur][k][64 + ty * 4];
            float4 b0 = *(const float4*)&Bs[cur][k][tx * 4];
            float4 b1 = *(const float4*)&Bs[cur][k][64 + tx * 4];
            float a[8] = {a0.x, a0.y, a0.z, a0.w, a1.x, a1.y, a1.z, a1.w};
            float b[8] = {b0.x, b0.y, b0.z, b0.w, b1.x, b1.y, b1.z, b1.w};
#pragma unroll
            for (int i = 0; i < 8; i++)
#pragma unroll
                for (int j = 0; j < 8; j++)
                    acc[i][j] = fmaf(a[i], b[j], acc[i][j]);
        }

        if (more) {
            const int nb = cur ^ 1;
            As[nb][ah + 0][arow] = tanhf(e2.x + p2.x);
            As[nb][ah + 1][arow] = tanhf(e2.y + p2.y);
            As[nb][ah + 2][arow] = tanhf(e2.z + p2.z);
            As[nb][ah + 3][arow] = tanhf(e2.w + p2.w);
            *(float4*)&Bs[nb][brow][bcol] = w2;
        }
        __syncthreads();
    }

    // ---- epilogue: + b_out, vectorized stores
    float4 bo0 = *(const float4*)(bout + n0 + tx * 4);
    float4 bo1 = *(const float4*)(bout + n0 + 64 + tx * 4);
#pragma unroll
    for (int i = 0; i < 8; i++) {
        const int ri = (i < 4) ? (ty * 4 + i) : (64 + ty * 4 + (i - 4));
        float* orow = out + (size_t)(m0 + ri) * VOCAB + n0;
        float4 v0, v1;
        v0.x = acc[i][0] + bo0.x;
        v0.y = acc[i][1] + bo0.y;
        v0.z = acc[i][2] + bo0.z;
        v0.w = acc[i][3] + bo0.w;
        v1.x = acc[i][4] + bo1.x;
        v1.y = acc[i][5] + bo1.y;
        v1.z = acc[i][6] + bo1.z;
        v1.w = acc[i][7] + bo1.w;
        *(float4*)(orow + tx * 4)      = v0;
        *(float4*)(orow + 64 + tx * 4) = v1;
    }
}

// ---------------------------------------------------------------------------
// Launch: inputs in metadata order:
//   0: enc_out [4,200,512]  1: pred_out [4,100,512]
//   2: W_enc [512,640]      3: b_enc [640]
//   4: W_pred [512,640]     5: W_out [640,1024]      6: b_out [1024]
// out: [4,200,100,1024] fp32
// ---------------------------------------------------------------------------
extern "C" void kernel_launch(void* const* d_in, const int* in_sizes, int n_in,
                              void* d_out, int out_size)
{
    const float* enc_out  = (const float*)d_in[0];
    const float* pred_out = (const float*)d_in[1];
    const float* W_enc    = (const float*)d_in[2];
    const float* b_enc    = (const float*)d_in[3];
    const float* W_pred   = (const float*)d_in[4];
    const float* W_out    = (const float*)d_in[5];
    const float* b_out    = (const float*)d_in[6];
    float* out = (float*)d_out;

    (void)in_sizes; (void)n_in; (void)out_size;

    // Stage 1: E = enc_out @ W_enc + b_enc   (M = 800)
    {
        dim3 grid(JOINT_DIM / 64, (B_DIM * T_DIM + 63) / 64);
        proj_kernel<0, true><<<grid, 256>>>(enc_out, W_enc, b_enc, B_DIM * T_DIM);
    }
    // Stage 2: P = pred_out @ W_pred         (M = 400)
    {
        dim3 grid(JOINT_DIM / 64, (B_DIM * U_DIM + 63) / 64);
        proj_kernel<1, false><<<grid, 256>>>(pred_out, W_pred, nullptr, B_DIM * U_DIM);
    }
    // Stage 3: fused tanh-joint GEMM -> logits
    {
        dim3 grid(VOCAB / 128, (B_DIM * T_DIM * U_DIM) / 128);  // 8 x 625
        joint_kernel<<<grid, 256>>>(W_out, b_out, out);
    }
}

// round 9
// speedup vs baseline: 2.1948x; 2.1948x over previous
#include <cuda_runtime.h>
#include <cuda_bf16.h>
#include <cstdint>

// ===========================================================================
// TransducerJoint via mma.sync bf16 (HMMA — tcgen05 PTX is rejected by the
// harness's compute_103 PTX stage, so we use the portable tensor-core path):
//   logits[b,t,u,v] = tanh(E[bt,:] + P[b,u,:]) @ W_out + b_out
//   B=4 T=200 U=100 ENC=512 JOINT=640 VOCAB=1024;  M=80000, N=1024, K=640
//
// Stage 1+2: E = enc@W_enc + b_enc ; P = pred@W_pred      (fp32 SIMT, tiny)
// Stage 2.5: W_out -> bf16 hi/lo, pre-packed into mma.sync B-fragment layout
// Stage 3:   fused tanh-joint GEMM, 3-MMA bf16 split, fp32 accumulation.
//
// R8 fix: g_Wf / wprep were sized for 10 K-chunks (R5's 64-wide geometry)
// while the GEMM consumes 20 chunks of 32 -> OOB read. Now 20 chunks.
// (R9: unchanged resubmit — R8 bench was an infra failure, not a kernel one.)
// ===========================================================================

#define B_DIM 4
#define T_DIM 200
#define U_DIM 100
#define ENC_DIM 512
#define JOINT_DIM 640
#define VOCAB 1024

__device__ float g_E[B_DIM * T_DIM * JOINT_DIM];   // [800,640]
__device__ float g_P[B_DIM * U_DIM * JOINT_DIM];   // [400,640]
// W_out fragments: [20 kchunks][8 nblocks] x 16KB (hi 8KB | lo 8KB)
__device__ __align__(16) unsigned char g_Wf[20 * 8 * 16384];

// ---------------------------------------------------------------------------
// helpers
// ---------------------------------------------------------------------------
__device__ __forceinline__ float tanh_fast(float x) {
    float r; asm("tanh.approx.f32 %0, %1;" : "=f"(r) : "f"(x)); return r;
}
// pack two fp32 -> bf16x2 (first arg -> low half = even-k element)
__device__ __forceinline__ uint32_t pack_bf(float lo, float hi) {
    uint32_t r; asm("cvt.rn.bf16x2.f32 %0, %1, %2;" : "=r"(r) : "f"(hi), "f"(lo));
    return r;
}
// residual pair given the hi pack
__device__ __forceinline__ uint32_t pack_bf_lo(float lo, float hi, uint32_t hp) {
    float hl = __uint_as_float(hp << 16);
    float hh = __uint_as_float(hp & 0xFFFF0000u);
    return pack_bf(lo - hl, hi - hh);
}
__device__ __forceinline__ void mma_bf16(float* c, const uint4& a, const uint2& b) {
    asm volatile(
        "mma.sync.aligned.m16n8k16.row.col.f32.bf16.bf16.f32 "
        "{%0,%1,%2,%3}, {%4,%5,%6,%7}, {%8,%9}, {%0,%1,%2,%3};"
        : "+f"(c[0]), "+f"(c[1]), "+f"(c[2]), "+f"(c[3])
        : "r"(a.x), "r"(a.y), "r"(a.z), "r"(a.w), "r"(b.x), "r"(b.y));
}

// ---------------------------------------------------------------------------
// Stage 1+2 fused: z=0 -> E (M=800, +bias), z=1 -> P (M=400, no bias).
// 64x64x16 fp32 tiles (same math as the passing R5 kernel).
// ---------------------------------------------------------------------------
__global__ __launch_bounds__(256)
void proj_kernel(const float* __restrict__ enc, const float* __restrict__ pred,
                 const float* __restrict__ W_enc, const float* __restrict__ W_pred,
                 const float* __restrict__ b_enc)
{
    const int z = blockIdx.z;
    const float* A    = z ? pred : enc;
    const float* W    = z ? W_pred : W_enc;
    const float* bias = z ? nullptr : b_enc;
    float* C          = z ? g_P : g_E;
    const int M       = z ? (B_DIM * U_DIM) : (B_DIM * T_DIM);

    const int BM = 64, BN = 64, BK = 16;
    const int m0 = blockIdx.y * BM;
    if (m0 >= M) return;
    const int n0 = blockIdx.x * BN;

    __shared__ float As[BK][BM];
    __shared__ float Bs[BK][BN];

    const int t  = threadIdx.x;
    const int tx = t & 15, ty = t >> 4;
    const int arow = t >> 2, ak = (t & 3) << 2;
    const int brow = t >> 4, bcol = (t & 15) << 2;

    float acc[4][4];
#pragma unroll
    for (int i = 0; i < 4; i++)
#pragma unroll
        for (int j = 0; j < 4; j++) acc[i][j] = 0.f;

    for (int k0 = 0; k0 < ENC_DIM; k0 += BK) {
        float4 av = make_float4(0.f, 0.f, 0.f, 0.f);
        if (m0 + arow < M)
            av = *(const float4*)(A + (size_t)(m0 + arow) * ENC_DIM + k0 + ak);
        As[ak + 0][arow] = av.x; As[ak + 1][arow] = av.y;
        As[ak + 2][arow] = av.z; As[ak + 3][arow] = av.w;
        *(float4*)&Bs[brow][bcol] =
            *(const float4*)(W + (size_t)(k0 + brow) * JOINT_DIM + n0 + bcol);
        __syncthreads();
#pragma unroll
        for (int k = 0; k < BK; k++) {
            float a[4], b[4];
#pragma unroll
            for (int i = 0; i < 4; i++) a[i] = As[k][ty * 4 + i];
#pragma unroll
            for (int j = 0; j < 4; j++) b[j] = Bs[k][tx * 4 + j];
#pragma unroll
            for (int i = 0; i < 4; i++)
#pragma unroll
                for (int j = 0; j < 4; j++)
                    acc[i][j] = fmaf(a[i], b[j], acc[i][j]);
        }
        __syncthreads();
    }
    float bv[4] = {0.f, 0.f, 0.f, 0.f};
    if (bias) {
        float4 b4 = *(const float4*)(bias + n0 + tx * 4);
        bv[0] = b4.x; bv[1] = b4.y; bv[2] = b4.z; bv[3] = b4.w;
    }
#pragma unroll
    for (int i = 0; i < 4; i++) {
        int row = m0 + ty * 4 + i;
        if (row < M) {
            float4 v;
            v.x = acc[i][0] + bv[0]; v.y = acc[i][1] + bv[1];
            v.z = acc[i][2] + bv[2]; v.w = acc[i][3] + bv[3];
            *(float4*)(C + (size_t)row * JOINT_DIM + n0 + tx * 4) = v;
        }
    }
}

// ---------------------------------------------------------------------------
// Stage 2.5: W_out[640,1024] -> mma.sync B-fragment layout, bf16 hi/lo.
// One thread per (kc, nb, natom, j, lane) = 163840 threads (20 K-chunks).
// Fragment: b0 = {W[k0][n], W[k0+1][n]}, b1 = {W[k0+8][n], W[k0+9][n]}
//   with n = nb*128 + natom*8 + (lane>>2), k0 = kc*32 + j*16 + (lane&3)*2.
// Dest: block (kc*8+nb)*16KB; hi at frag*8, lo at 8192+frag*8,
//   frag = (natom*2 + j)*32 + lane.
// ---------------------------------------------------------------------------
__global__ __launch_bounds__(256)
void wprep_kernel(const float* __restrict__ W)
{
    int id    = blockIdx.x * 256 + threadIdx.x;    // 0..163839
    int lane  = id & 31;
    int j     = (id >> 5) & 1;
    int natom = (id >> 6) & 15;
    int nb    = (id >> 10) & 7;
    int kc    = id >> 13;                           // 0..19

    int n  = nb * 128 + natom * 8 + (lane >> 2);
    int k0 = kc * 32 + j * 16 + (lane & 3) * 2;

    float w0 = W[(size_t)(k0 + 0) * VOCAB + n];
    float w1 = W[(size_t)(k0 + 1) * VOCAB + n];
    float w8 = W[(size_t)(k0 + 8) * VOCAB + n];
    float w9 = W[(size_t)(k0 + 9) * VOCAB + n];

    uint32_t h0 = pack_bf(w0, w1), h1 = pack_bf(w8, w9);
    uint32_t l0 = pack_bf_lo(w0, w1, h0), l1 = pack_bf_lo(w8, w9, h1);

    size_t blk  = (size_t)(kc * 8 + nb) * 16384;
    size_t frag = (size_t)((natom * 2 + j) * 32 + lane) * 8;
    *(uint2*)(g_Wf + blk + frag)        = make_uint2(h0, h1);
    *(uint2*)(g_Wf + blk + 8192 + frag) = make_uint2(l0, l1);
}

// ---------------------------------------------------------------------------
// Stage 3: fused joint GEMM on mma.sync bf16.
// Grid (8, 625), 256 threads. CTA tile 128x128, BK=32, double-buffered SMEM.
// Buffer (32KB): Ahi 8K | Alo 8K | Bhi 8K | Blo 8K.  A fragments generated
// from tanh(E+P) directly in register layout; B copied pre-packed from g_Wf.
// ---------------------------------------------------------------------------
#define SMEM_NEED 65536

__global__ __launch_bounds__(256, 1)
void joint_mma_kernel(const float* __restrict__ bout, float* __restrict__ out)
{
    extern __shared__ char smem[];

    const int t    = threadIdx.x;
    const int lane = t & 31;
    const int wid  = t >> 5;
    const int wy   = wid >> 1;          // 0..3  (M)
    const int wx   = wid & 1;           // 0..1  (N)
    const int g    = lane >> 2;         // groupID
    const int tg   = lane & 3;          // threadID in group
    const int m0   = blockIdx.y * 128;
    const int n0   = blockIdx.x * 128;
    const int bx   = blockIdx.x;

    // ---- A producer per-thread geometry: m-atom pi = wid, rows r0/r0+8
    const int pi = wid;
    const int r0 = m0 + pi * 16 + g;
    const int r1 = r0 + 8;
    const int bt0 = r0 / U_DIM, u0 = r0 - bt0 * U_DIM, bb0 = bt0 / T_DIM;
    const int bt1 = r1 / U_DIM, u1 = r1 - bt1 * U_DIM, bb1 = bt1 / T_DIM;
    const float* E0 = g_E + (size_t)bt0 * JOINT_DIM;
    const float* P0 = g_P + (size_t)(bb0 * U_DIM + u0) * JOINT_DIM;
    const float* E1 = g_E + (size_t)bt1 * JOINT_DIM;
    const float* P1 = g_P + (size_t)(bb1 * U_DIM + u1) * JOINT_DIM;

    float acc[2][8][4];
#pragma unroll
    for (int ma = 0; ma < 2; ma++)
#pragma unroll
        for (int na = 0; na < 8; na++)
#pragma unroll
            for (int q = 0; q < 4; q++) acc[ma][na][q] = 0.f;

    // producer convert+store into dst buffer from prefetched registers
    auto convert_store = [&](char* dst, const float2 (&e0)[4], const float2 (&p0)[4],
                             const float2 (&e1)[4], const float2 (&p1)[4],
                             const uint4 (&wv)[4]) {
        uint4* Ah = (uint4*)dst;
        uint4* Al = (uint4*)(dst + 8192);
#pragma unroll
        for (int j = 0; j < 2; j++) {
            // q = j*2 + h : h=0 -> k0..k0+1, h=1 -> k0+8..k0+9
            float x00 = tanh_fast(e0[j * 2 + 0].x + p0[j * 2 + 0].x);
            float x01 = tanh_fast(e0[j * 2 + 0].y + p0[j * 2 + 0].y);
            float x08 = tanh_fast(e0[j * 2 + 1].x + p0[j * 2 + 1].x);
            float x09 = tanh_fast(e0[j * 2 + 1].y + p0[j * 2 + 1].y);
            float x10 = tanh_fast(e1[j * 2 + 0].x + p1[j * 2 + 0].x);
            float x11 = tanh_fast(e1[j * 2 + 0].y + p1[j * 2 + 0].y);
            float x18 = tanh_fast(e1[j * 2 + 1].x + p1[j * 2 + 1].x);
            float x19 = tanh_fast(e1[j * 2 + 1].y + p1[j * 2 + 1].y);
            uint32_t a0 = pack_bf(x00, x01);
            uint32_t a1 = pack_bf(x10, x11);
            uint32_t a2 = pack_bf(x08, x09);
            uint32_t a3 = pack_bf(x18, x19);
            uint32_t b0 = pack_bf_lo(x00, x01, a0);
            uint32_t b1 = pack_bf_lo(x10, x11, a1);
            uint32_t b2 = pack_bf_lo(x08, x09, a2);
            uint32_t b3 = pack_bf_lo(x18, x19, a3);
            const int idx = (pi * 2 + j) * 32 + lane;
            Ah[idx] = make_uint4(a0, a1, a2, a3);
            Al[idx] = make_uint4(b0, b1, b2, b3);
        }
        uint4* Bd = (uint4*)(dst + 16384);
#pragma unroll
        for (int i = 0; i < 4; i++) Bd[i * 256 + t] = wv[i];
    };
    auto prefetch = [&](int kc, float2 (&e0)[4], float2 (&p0)[4],
                        float2 (&e1)[4], float2 (&p1)[4], uint4 (&wv)[4]) {
        const int K0 = kc * 32;
#pragma unroll
        for (int q = 0; q < 4; q++) {
            const int off = K0 + (q >> 1) * 16 + tg * 2 + (q & 1) * 8;
            e0[q] = *(const float2*)(E0 + off);
            p0[q] = *(const float2*)(P0 + off);
            e1[q] = *(const float2*)(E1 + off);
            p1[q] = *(const float2*)(P1 + off);
        }
        const uint4* ws = (const uint4*)(g_Wf) + (size_t)(kc * 8 + bx) * 1024;
#pragma unroll
        for (int i = 0; i < 4; i++) wv[i] = ws[i * 256 + t];
    };

    // ---- prologue: produce chunk 0
    {
        float2 e0[4], p0[4], e1[4], p1[4]; uint4 wv[4];
        prefetch(0, e0, p0, e1, p1, wv);
        convert_store(smem, e0, p0, e1, p1, wv);
    }
    __syncthreads();

#pragma unroll 1
    for (int kc = 0; kc < 20; kc++) {
        char* cbuf = smem + (kc & 1) * 32768;
        char* nbuf = smem + ((kc + 1) & 1) * 32768;
        const bool more = (kc < 19);

        float2 e0[4], p0[4], e1[4], p1[4]; uint4 wv[4];
        if (more) prefetch(kc + 1, e0, p0, e1, p1, wv);

        const uint4* Ah = (const uint4*)cbuf;
        const uint4* Al = (const uint4*)(cbuf + 8192);
        const uint2* Bh = (const uint2*)(cbuf + 16384);
        const uint2* Bl = (const uint2*)(cbuf + 24576);
#pragma unroll
        for (int j = 0; j < 2; j++) {
            uint4 ah[2], al[2];
#pragma unroll
            for (int ma = 0; ma < 2; ma++) {
                const int idx = ((wy * 2 + ma) * 2 + j) * 32 + lane;
                ah[ma] = Ah[idx];
                al[ma] = Al[idx];
            }
            uint2 bh[8], bl[8];
#pragma unroll
            for (int na = 0; na < 8; na++) {
                const int idx = ((wx * 8 + na) * 2 + j) * 32 + lane;
                bh[na] = Bh[idx];
                bl[na] = Bl[idx];
            }
#pragma unroll
            for (int ma = 0; ma < 2; ma++)
#pragma unroll
                for (int na = 0; na < 8; na++) {
                    mma_bf16(acc[ma][na], ah[ma], bh[na]);   // hi*hi
                    mma_bf16(acc[ma][na], ah[ma], bl[na]);   // hi*lo
                    mma_bf16(acc[ma][na], al[ma], bh[na]);   // lo*hi
                }
        }

        if (more) convert_store(nbuf, e0, p0, e1, p1, wv);
        __syncthreads();
    }

    // ---- epilogue: bias + streaming float2 stores (full 32B sectors)
    float2 bias2[8];
#pragma unroll
    for (int na = 0; na < 8; na++)
        bias2[na] = *(const float2*)(bout + n0 + wx * 64 + na * 8 + tg * 2);

#pragma unroll
    for (int ma = 0; ma < 2; ma++) {
        const int ra = m0 + wy * 32 + ma * 16 + g;
        float* rowa = out + (size_t)ra * VOCAB + n0 + wx * 64;
        float* rowb = rowa + (size_t)8 * VOCAB;
#pragma unroll
        for (int na = 0; na < 8; na++) {
            float2 va, vb;
            va.x = acc[ma][na][0] + bias2[na].x;
            va.y = acc[ma][na][1] + bias2[na].y;
            vb.x = acc[ma][na][2] + bias2[na].x;
            vb.y = acc[ma][na][3] + bias2[na].y;
            __stcs((float2*)(rowa + na * 8 + tg * 2), va);
            __stcs((float2*)(rowb + na * 8 + tg * 2), vb);
        }
    }
}

// ---------------------------------------------------------------------------
// Launch. Inputs: 0 enc_out, 1 pred_out, 2 W_enc, 3 b_enc, 4 W_pred,
//                 5 W_out, 6 b_out.  Output fp32 [4,200,100,1024].
// ---------------------------------------------------------------------------
extern "C" void kernel_launch(void* const* d_in, const int* in_sizes, int n_in,
                              void* d_out, int out_size)
{
    const float* enc_out  = (const float*)d_in[0];
    const float* pred_out = (const float*)d_in[1];
    const float* W_enc    = (const float*)d_in[2];
    const float* b_enc    = (const float*)d_in[3];
    const float* W_pred   = (const float*)d_in[4];
    const float* W_out    = (const float*)d_in[5];
    const float* b_out    = (const float*)d_in[6];
    float* out = (float*)d_out;
    (void)in_sizes; (void)n_in; (void)out_size;

    cudaFuncSetAttribute(joint_mma_kernel,
                         cudaFuncAttributeMaxDynamicSharedMemorySize, SMEM_NEED);

    // Stage 1+2: both projections (z selects E vs P).
    {
        dim3 grid(JOINT_DIM / 64, (B_DIM * T_DIM + 63) / 64, 2);
        proj_kernel<<<grid, 256>>>(enc_out, pred_out, W_enc, W_pred, b_enc);
    }
    // Stage 2.5: W_out -> bf16 hi/lo fragment streams (20 K-chunks).
    wprep_kernel<<<640, 256>>>(W_out);
    // Stage 3: tensor-core fused joint GEMM.
    {
        dim3 grid(VOCAB / 128, (B_DIM * T_DIM * U_DIM) / 128);   // 8 x 625
        joint_mma_kernel<<<grid, 256, SMEM_NEED>>>(b_out, out);
    }
}

// round 10
// speedup vs baseline: 2.8571x; 1.3018x over previous
#include <cuda_runtime.h>
#include <cuda_fp16.h>
#include <cstdint>

// ===========================================================================
// TransducerJoint via mma.sync fp16 (HMMA):
//   logits[b,t,u,v] = tanh(E[bt,:] + P[b,u,:]) @ W_out + b_out
//   B=4 T=200 U=100 ENC=512 JOINT=640 VOCAB=1024;  M=80000, N=1024, K=640
//
// R10 design:
//  - fp16 2-MMA split: A = a_hi + a_lo (fp16 pair, exact to ~2^-22),
//    B = single fp16. Error ~= b rounding (2^-11 random) -> norm rel ~2.5e-4.
//  - CTA tile 128(M) x 256(N), 8 warps of 64x64 (ma=4, na=8), BK=32,
//    double-buffered SMEM (2 x 32KB: Ahi 8K | Alo 8K | B 16K).
//  - B pre-packed in fragment layout (wprep), loaded via cp.async.
//  - A generated in-kernel: tanh(E+P) straight into fragment layout.
// ===========================================================================

#define B_DIM 4
#define T_DIM 200
#define U_DIM 100
#define ENC_DIM 512
#define JOINT_DIM 640
#define VOCAB 1024

__device__ float g_E[B_DIM * T_DIM * JOINT_DIM];   // [800,640]
__device__ float g_P[B_DIM * U_DIM * JOINT_DIM];   // [400,640]
// W_out fp16 fragments: [20 kchunks][4 nblocks(256)] x 16KB
__device__ __align__(16) unsigned char g_Wf[20 * 4 * 16384];

// ---------------------------------------------------------------------------
// helpers
// ---------------------------------------------------------------------------
__device__ __forceinline__ uint32_t smem_u32(const void* p) {
    uint32_t a;
    asm("{ .reg .u64 t; cvta.to.shared.u64 t, %1; cvt.u32.u64 %0, t; }"
        : "=r"(a) : "l"(p));
    return a;
}
__device__ __forceinline__ float tanh_fast(float x) {
    float r; asm("tanh.approx.f32 %0, %1;" : "=f"(r) : "f"(x)); return r;
}
// pack two fp32 -> f16x2 (first arg -> LOW half = even-k element)
__device__ __forceinline__ uint32_t pack_h(float lo, float hi) {
    uint32_t r; asm("cvt.rn.f16x2.f32 %0, %1, %2;" : "=r"(r) : "f"(hi), "f"(lo));
    return r;
}
// residual pair given the hi pack
__device__ __forceinline__ uint32_t pack_h_lo(float lo, float hi, uint32_t hp) {
    __half2 h = *reinterpret_cast<__half2*>(&hp);
    float2 f = __half22float2(h);
    return pack_h(lo - f.x, hi - f.y);
}
__device__ __forceinline__ void mma_f16(float* c, const uint4& a, const uint2& b) {
    asm volatile(
        "mma.sync.aligned.m16n8k16.row.col.f32.f16.f16.f32 "
        "{%0,%1,%2,%3}, {%4,%5,%6,%7}, {%8,%9}, {%0,%1,%2,%3};"
        : "+f"(c[0]), "+f"(c[1]), "+f"(c[2]), "+f"(c[3])
        : "r"(a.x), "r"(a.y), "r"(a.z), "r"(a.w), "r"(b.x), "r"(b.y));
}
#define CP_ASYNC16(dst, src) \
    asm volatile("cp.async.cg.shared.global [%0], [%1], 16;" \
                 :: "r"(dst), "l"(src) : "memory")
#define CP_COMMIT() asm volatile("cp.async.commit_group;" ::: "memory")
#define CP_WAIT0()  asm volatile("cp.async.wait_group 0;" ::: "memory")

// ---------------------------------------------------------------------------
// Stage 1+2 fused: z=0 -> E (M=800, +bias), z=1 -> P (M=400, no bias).
// 64x64x16 fp32 tiles (unchanged from the passing R9 kernel).
// ---------------------------------------------------------------------------
__global__ __launch_bounds__(256)
void proj_kernel(const float* __restrict__ enc, const float* __restrict__ pred,
                 const float* __restrict__ W_enc, const float* __restrict__ W_pred,
                 const float* __restrict__ b_enc)
{
    const int z = blockIdx.z;
    const float* A    = z ? pred : enc;
    const float* W    = z ? W_pred : W_enc;
    const float* bias = z ? nullptr : b_enc;
    float* C          = z ? g_P : g_E;
    const int M       = z ? (B_DIM * U_DIM) : (B_DIM * T_DIM);

    const int BM = 64, BN = 64, BK = 16;
    const int m0 = blockIdx.y * BM;
    if (m0 >= M) return;
    const int n0 = blockIdx.x * BN;

    __shared__ float As[BK][BM];
    __shared__ float Bs[BK][BN];

    const int t  = threadIdx.x;
    const int tx = t & 15, ty = t >> 4;
    const int arow = t >> 2, ak = (t & 3) << 2;
    const int brow = t >> 4, bcol = (t & 15) << 2;

    float acc[4][4];
#pragma unroll
    for (int i = 0; i < 4; i++)
#pragma unroll
        for (int j = 0; j < 4; j++) acc[i][j] = 0.f;

    for (int k0 = 0; k0 < ENC_DIM; k0 += BK) {
        float4 av = make_float4(0.f, 0.f, 0.f, 0.f);
        if (m0 + arow < M)
            av = *(const float4*)(A + (size_t)(m0 + arow) * ENC_DIM + k0 + ak);
        As[ak + 0][arow] = av.x; As[ak + 1][arow] = av.y;
        As[ak + 2][arow] = av.z; As[ak + 3][arow] = av.w;
        *(float4*)&Bs[brow][bcol] =
            *(const float4*)(W + (size_t)(k0 + brow) * JOINT_DIM + n0 + bcol);
        __syncthreads();
#pragma unroll
        for (int k = 0; k < BK; k++) {
            float a[4], b[4];
#pragma unroll
            for (int i = 0; i < 4; i++) a[i] = As[k][ty * 4 + i];
#pragma unroll
            for (int j = 0; j < 4; j++) b[j] = Bs[k][tx * 4 + j];
#pragma unroll
            for (int i = 0; i < 4; i++)
#pragma unroll
                for (int j = 0; j < 4; j++)
                    acc[i][j] = fmaf(a[i], b[j], acc[i][j]);
        }
        __syncthreads();
    }
    float bv[4] = {0.f, 0.f, 0.f, 0.f};
    if (bias) {
        float4 b4 = *(const float4*)(bias + n0 + tx * 4);
        bv[0] = b4.x; bv[1] = b4.y; bv[2] = b4.z; bv[3] = b4.w;
    }
#pragma unroll
    for (int i = 0; i < 4; i++) {
        int row = m0 + ty * 4 + i;
        if (row < M) {
            float4 v;
            v.x = acc[i][0] + bv[0]; v.y = acc[i][1] + bv[1];
            v.z = acc[i][2] + bv[2]; v.w = acc[i][3] + bv[3];
            *(float4*)(C + (size_t)row * JOINT_DIM + n0 + tx * 4) = v;
        }
    }
}

// ---------------------------------------------------------------------------
// Stage 2.5: W_out[640,1024] -> single-fp16 mma.sync B-fragment layout.
// One thread per (kc, nbx, natom, j, lane) = 163840.
//   n  = nbx*256 + natom*8 + (lane>>2)
//   k0 = kc*32 + j*16 + (lane&3)*2
//   frag uint2 {pack(W[k0][n],W[k0+1][n]), pack(W[k0+8][n],W[k0+9][n])}
//   at block (kc*4+nbx)*16KB, offset ((natom*2+j)*32+lane)*8.
// ---------------------------------------------------------------------------
__global__ __launch_bounds__(256)
void wprep_kernel(const float* __restrict__ W)
{
    int id    = blockIdx.x * 256 + threadIdx.x;    // 0..163839
    int lane  = id & 31;
    int j     = (id >> 5) & 1;
    int natom = (id >> 6) & 31;
    int nbx   = (id >> 11) & 3;
    int kc    = id >> 13;                           // 0..19

    int n  = nbx * 256 + natom * 8 + (lane >> 2);
    int k0 = kc * 32 + j * 16 + (lane & 3) * 2;

    float w0 = W[(size_t)(k0 + 0) * VOCAB + n];
    float w1 = W[(size_t)(k0 + 1) * VOCAB + n];
    float w8 = W[(size_t)(k0 + 8) * VOCAB + n];
    float w9 = W[(size_t)(k0 + 9) * VOCAB + n];

    size_t blk  = (size_t)(kc * 4 + nbx) * 16384;
    size_t frag = (size_t)((natom * 2 + j) * 32 + lane) * 8;
    *(uint2*)(g_Wf + blk + frag) = make_uint2(pack_h(w0, w1), pack_h(w8, w9));
}

// ---------------------------------------------------------------------------
// Stage 3: fused joint GEMM, fp16 2-MMA split.
// Grid (4, 625), 256 threads. CTA tile 128x256, 8 warps (wy=wid>>2, wx=wid&3),
// warp tile 64x64. BK=32, double buffer: [Ahi 8K | Alo 8K | B 16K] x 2.
// ---------------------------------------------------------------------------
#define BUF_BYTES 32768
#define SMEM_NEED 65536

__global__ __launch_bounds__(256, 1)
void joint_mma_kernel(const float* __restrict__ bout, float* __restrict__ out)
{
    extern __shared__ char smem[];

    const int t    = threadIdx.x;
    const int lane = t & 31;
    const int wid  = t >> 5;
    const int wy   = wid >> 2;          // 0..1  (M, 64 rows each)
    const int wx   = wid & 3;           // 0..3  (N, 64 cols each)
    const int g    = lane >> 2;
    const int tg   = lane & 3;
    const int m0   = blockIdx.y * 128;
    const int n0   = blockIdx.x * 256;
    const int bx   = blockIdx.x;

    // ---- A producer geometry: atom pi = wid (8 atoms = 128 rows)
    const int pi = wid;
    const int r0 = m0 + pi * 16 + g;
    const int r1 = r0 + 8;
    const int bt0 = r0 / U_DIM, u0 = r0 - bt0 * U_DIM, bb0 = bt0 / T_DIM;
    const int bt1 = r1 / U_DIM, u1 = r1 - bt1 * U_DIM, bb1 = bt1 / T_DIM;
    const float* E0 = g_E + (size_t)bt0 * JOINT_DIM;
    const float* P0 = g_P + (size_t)(bb0 * U_DIM + u0) * JOINT_DIM;
    const float* E1 = g_E + (size_t)bt1 * JOINT_DIM;
    const float* P1 = g_P + (size_t)(bb1 * U_DIM + u1) * JOINT_DIM;

    float acc[4][8][4];
#pragma unroll
    for (int ma = 0; ma < 4; ma++)
#pragma unroll
        for (int na = 0; na < 8; na++)
#pragma unroll
            for (int q = 0; q < 4; q++) acc[ma][na][q] = 0.f;

    auto prefetchA = [&](int kc, float2 (&e0)[4], float2 (&p0)[4],
                         float2 (&e1)[4], float2 (&p1)[4]) {
        const int K0 = kc * 32;
#pragma unroll
        for (int q = 0; q < 4; q++) {
            const int off = K0 + (q >> 1) * 16 + tg * 2 + (q & 1) * 8;
            e0[q] = *(const float2*)(E0 + off);
            p0[q] = *(const float2*)(P0 + off);
            e1[q] = *(const float2*)(E1 + off);
            p1[q] = *(const float2*)(P1 + off);
        }
    };
    auto storeA = [&](char* buf, const float2 (&e0)[4], const float2 (&p0)[4],
                      const float2 (&e1)[4], const float2 (&p1)[4]) {
        uint4* Ah = (uint4*)buf;
        uint4* Al = (uint4*)(buf + 8192);
#pragma unroll
        for (int j = 0; j < 2; j++) {
            float x00 = tanh_fast(e0[j * 2 + 0].x + p0[j * 2 + 0].x);
            float x01 = tanh_fast(e0[j * 2 + 0].y + p0[j * 2 + 0].y);
            float x08 = tanh_fast(e0[j * 2 + 1].x + p0[j * 2 + 1].x);
            float x09 = tanh_fast(e0[j * 2 + 1].y + p0[j * 2 + 1].y);
            float x10 = tanh_fast(e1[j * 2 + 0].x + p1[j * 2 + 0].x);
            float x11 = tanh_fast(e1[j * 2 + 0].y + p1[j * 2 + 0].y);
            float x18 = tanh_fast(e1[j * 2 + 1].x + p1[j * 2 + 1].x);
            float x19 = tanh_fast(e1[j * 2 + 1].y + p1[j * 2 + 1].y);
            uint32_t a0 = pack_h(x00, x01);
            uint32_t a1 = pack_h(x10, x11);
            uint32_t a2 = pack_h(x08, x09);
            uint32_t a3 = pack_h(x18, x19);
            uint32_t b0 = pack_h_lo(x00, x01, a0);
            uint32_t b1 = pack_h_lo(x10, x11, a1);
            uint32_t b2 = pack_h_lo(x08, x09, a2);
            uint32_t b3 = pack_h_lo(x18, x19, a3);
            const int idx = (pi * 2 + j) * 32 + lane;
            Ah[idx] = make_uint4(a0, a1, a2, a3);
            Al[idx] = make_uint4(b0, b1, b2, b3);
        }
    };
    auto issueB = [&](int kc, char* buf) {
        const char* src = (const char*)g_Wf + (size_t)(kc * 4 + bx) * 16384
                        + (size_t)t * 64;
        uint32_t dst = smem_u32(buf + 16384 + t * 64);
#pragma unroll
        for (int i = 0; i < 4; i++)
            CP_ASYNC16(dst + i * 16, src + i * 16);
    };

    // ---- prologue: fill buffer 0
    {
        issueB(0, smem);
        CP_COMMIT();
        float2 e0[4], p0[4], e1[4], p1[4];
        prefetchA(0, e0, p0, e1, p1);
        storeA(smem, e0, p0, e1, p1);
        CP_WAIT0();
    }
    __syncthreads();

#pragma unroll 1
    for (int kc = 0; kc < 20; kc++) {
        char* cbuf = smem + (kc & 1) * BUF_BYTES;
        char* nbuf = smem + ((kc + 1) & 1) * BUF_BYTES;
        const bool more = (kc < 19);

        float2 e0[4], p0[4], e1[4], p1[4];
        if (more) {
            issueB(kc + 1, nbuf);
            CP_COMMIT();
            prefetchA(kc + 1, e0, p0, e1, p1);
        }

        const uint4* Ah = (const uint4*)cbuf;
        const uint4* Al = (const uint4*)(cbuf + 8192);
        const uint2* Bf = (const uint2*)(cbuf + 16384);
#pragma unroll
        for (int j = 0; j < 2; j++) {
            uint2 bf[8];
#pragma unroll
            for (int na = 0; na < 8; na++)
                bf[na] = Bf[((wx * 8 + na) * 2 + j) * 32 + lane];
#pragma unroll
            for (int ma = 0; ma < 4; ma++) {
                const int aidx = ((wy * 4 + ma) * 2 + j) * 32 + lane;
                uint4 ah = Ah[aidx];
                uint4 al = Al[aidx];
#pragma unroll
                for (int na = 0; na < 8; na++) {
                    mma_f16(acc[ma][na], ah, bf[na]);   // hi * b
                    mma_f16(acc[ma][na], al, bf[na]);   // lo * b
                }
            }
        }

        if (more) {
            storeA(nbuf, e0, p0, e1, p1);
            CP_WAIT0();
        }
        __syncthreads();
    }

    // ---- epilogue: bias + streaming float2 stores
    float2 bias2[8];
#pragma unroll
    for (int na = 0; na < 8; na++)
        bias2[na] = *(const float2*)(bout + n0 + wx * 64 + na * 8 + tg * 2);

#pragma unroll
    for (int ma = 0; ma < 4; ma++) {
        const int ra = m0 + wy * 64 + ma * 16 + g;
        float* rowa = out + (size_t)ra * VOCAB + n0 + wx * 64;
        float* rowb = rowa + (size_t)8 * VOCAB;
#pragma unroll
        for (int na = 0; na < 8; na++) {
            float2 va, vb;
            va.x = acc[ma][na][0] + bias2[na].x;
            va.y = acc[ma][na][1] + bias2[na].y;
            vb.x = acc[ma][na][2] + bias2[na].x;
            vb.y = acc[ma][na][3] + bias2[na].y;
            __stcs((float2*)(rowa + na * 8 + tg * 2), va);
            __stcs((float2*)(rowb + na * 8 + tg * 2), vb);
        }
    }
}

// ---------------------------------------------------------------------------
// Launch. Inputs: 0 enc_out, 1 pred_out, 2 W_enc, 3 b_enc, 4 W_pred,
//                 5 W_out, 6 b_out.  Output fp32 [4,200,100,1024].
// ---------------------------------------------------------------------------
extern "C" void kernel_launch(void* const* d_in, const int* in_sizes, int n_in,
                              void* d_out, int out_size)
{
    const float* enc_out  = (const float*)d_in[0];
    const float* pred_out = (const float*)d_in[1];
    const float* W_enc    = (const float*)d_in[2];
    const float* b_enc    = (const float*)d_in[3];
    const float* W_pred   = (const float*)d_in[4];
    const float* W_out    = (const float*)d_in[5];
    const float* b_out    = (const float*)d_in[6];
    float* out = (float*)d_out;
    (void)in_sizes; (void)n_in; (void)out_size;

    cudaFuncSetAttribute(joint_mma_kernel,
                         cudaFuncAttributeMaxDynamicSharedMemorySize, SMEM_NEED);

    // Stage 1+2: both projections (z selects E vs P).
    {
        dim3 grid(JOINT_DIM / 64, (B_DIM * T_DIM + 63) / 64, 2);
        proj_kernel<<<grid, 256>>>(enc_out, pred_out, W_enc, W_pred, b_enc);
    }
    // Stage 2.5: W_out -> fp16 fragment stream (20 kchunks x 4 nblocks).
    wprep_kernel<<<640, 256>>>(W_out);
    // Stage 3: tensor-core fused joint GEMM.
    {
        dim3 grid(VOCAB / 256, (B_DIM * T_DIM * U_DIM) / 128);   // 4 x 625
        joint_mma_kernel<<<grid, 256, SMEM_NEED>>>(b_out, out);
    }
}

// round 11
// speedup vs baseline: 2.9158x; 1.0205x over previous
#include <cuda_runtime.h>
#include <cuda_fp16.h>
#include <cstdint>

// ===========================================================================
// TransducerJoint via mma.sync fp16 (HMMA):
//   logits[b,t,u,v] = tanh(E[bt,:] + P[b,u,:]) @ W_out + b_out
//   B=4 T=200 U=100 ENC=512 JOINT=640 VOCAB=1024;  M=80000, N=1024, K=640
//
// R11: same fp16 2-MMA-split numerics as R10 (rel_err 2.07e-4), but the joint
// kernel now runs 512 threads / 16 warps per CTA (4 warps/SMSP instead of 2)
// with warp tile 32x64 — pure latency-hiding change; R10 was ~3.7x over the
// HMMA issue floor from exposed LDG/cp.async/barrier latency at 2 warps/SMSP.
// ===========================================================================

#define B_DIM 4
#define T_DIM 200
#define U_DIM 100
#define ENC_DIM 512
#define JOINT_DIM 640
#define VOCAB 1024

__device__ float g_E[B_DIM * T_DIM * JOINT_DIM];   // [800,640]
__device__ float g_P[B_DIM * U_DIM * JOINT_DIM];   // [400,640]
// W_out fp16 fragments: [20 kchunks][4 nblocks(256)] x 16KB
__device__ __align__(16) unsigned char g_Wf[20 * 4 * 16384];

// ---------------------------------------------------------------------------
// helpers
// ---------------------------------------------------------------------------
__device__ __forceinline__ uint32_t smem_u32(const void* p) {
    uint32_t a;
    asm("{ .reg .u64 t; cvta.to.shared.u64 t, %1; cvt.u32.u64 %0, t; }"
        : "=r"(a) : "l"(p));
    return a;
}
__device__ __forceinline__ float tanh_fast(float x) {
    float r; asm("tanh.approx.f32 %0, %1;" : "=f"(r) : "f"(x)); return r;
}
// pack two fp32 -> f16x2 (first arg -> LOW half = even-k element)
__device__ __forceinline__ uint32_t pack_h(float lo, float hi) {
    uint32_t r; asm("cvt.rn.f16x2.f32 %0, %1, %2;" : "=r"(r) : "f"(hi), "f"(lo));
    return r;
}
// residual pair given the hi pack
__device__ __forceinline__ uint32_t pack_h_lo(float lo, float hi, uint32_t hp) {
    __half2 h = *reinterpret_cast<__half2*>(&hp);
    float2 f = __half22float2(h);
    return pack_h(lo - f.x, hi - f.y);
}
__device__ __forceinline__ void mma_f16(float* c, const uint4& a, const uint2& b) {
    asm volatile(
        "mma.sync.aligned.m16n8k16.row.col.f32.f16.f16.f32 "
        "{%0,%1,%2,%3}, {%4,%5,%6,%7}, {%8,%9}, {%0,%1,%2,%3};"
        : "+f"(c[0]), "+f"(c[1]), "+f"(c[2]), "+f"(c[3])
        : "r"(a.x), "r"(a.y), "r"(a.z), "r"(a.w), "r"(b.x), "r"(b.y));
}
#define CP_ASYNC16(dst, src) \
    asm volatile("cp.async.cg.shared.global [%0], [%1], 16;" \
                 :: "r"(dst), "l"(src) : "memory")
#define CP_COMMIT() asm volatile("cp.async.commit_group;" ::: "memory")
#define CP_WAIT0()  asm volatile("cp.async.wait_group 0;" ::: "memory")

// ---------------------------------------------------------------------------
// Stage 1+2 fused: z=0 -> E (M=800, +bias), z=1 -> P (M=400, no bias).
// 64x64x16 fp32 tiles (unchanged from the passing R9/R10 kernels).
// ---------------------------------------------------------------------------
__global__ __launch_bounds__(256)
void proj_kernel(const float* __restrict__ enc, const float* __restrict__ pred,
                 const float* __restrict__ W_enc, const float* __restrict__ W_pred,
                 const float* __restrict__ b_enc)
{
    const int z = blockIdx.z;
    const float* A    = z ? pred : enc;
    const float* W    = z ? W_pred : W_enc;
    const float* bias = z ? nullptr : b_enc;
    float* C          = z ? g_P : g_E;
    const int M       = z ? (B_DIM * U_DIM) : (B_DIM * T_DIM);

    const int BM = 64, BN = 64, BK = 16;
    const int m0 = blockIdx.y * BM;
    if (m0 >= M) return;
    const int n0 = blockIdx.x * BN;

    __shared__ float As[BK][BM];
    __shared__ float Bs[BK][BN];

    const int t  = threadIdx.x;
    const int tx = t & 15, ty = t >> 4;
    const int arow = t >> 2, ak = (t & 3) << 2;
    const int brow = t >> 4, bcol = (t & 15) << 2;

    float acc[4][4];
#pragma unroll
    for (int i = 0; i < 4; i++)
#pragma unroll
        for (int j = 0; j < 4; j++) acc[i][j] = 0.f;

    for (int k0 = 0; k0 < ENC_DIM; k0 += BK) {
        float4 av = make_float4(0.f, 0.f, 0.f, 0.f);
        if (m0 + arow < M)
            av = *(const float4*)(A + (size_t)(m0 + arow) * ENC_DIM + k0 + ak);
        As[ak + 0][arow] = av.x; As[ak + 1][arow] = av.y;
        As[ak + 2][arow] = av.z; As[ak + 3][arow] = av.w;
        *(float4*)&Bs[brow][bcol] =
            *(const float4*)(W + (size_t)(k0 + brow) * JOINT_DIM + n0 + bcol);
        __syncthreads();
#pragma unroll
        for (int k = 0; k < BK; k++) {
            float a[4], b[4];
#pragma unroll
            for (int i = 0; i < 4; i++) a[i] = As[k][ty * 4 + i];
#pragma unroll
            for (int j = 0; j < 4; j++) b[j] = Bs[k][tx * 4 + j];
#pragma unroll
            for (int i = 0; i < 4; i++)
#pragma unroll
                for (int j = 0; j < 4; j++)
                    acc[i][j] = fmaf(a[i], b[j], acc[i][j]);
        }
        __syncthreads();
    }
    float bv[4] = {0.f, 0.f, 0.f, 0.f};
    if (bias) {
        float4 b4 = *(const float4*)(bias + n0 + tx * 4);
        bv[0] = b4.x; bv[1] = b4.y; bv[2] = b4.z; bv[3] = b4.w;
    }
#pragma unroll
    for (int i = 0; i < 4; i++) {
        int row = m0 + ty * 4 + i;
        if (row < M) {
            float4 v;
            v.x = acc[i][0] + bv[0]; v.y = acc[i][1] + bv[1];
            v.z = acc[i][2] + bv[2]; v.w = acc[i][3] + bv[3];
            *(float4*)(C + (size_t)row * JOINT_DIM + n0 + tx * 4) = v;
        }
    }
}

// ---------------------------------------------------------------------------
// Stage 2.5: W_out[640,1024] -> single-fp16 mma.sync B-fragment layout.
// (unchanged from R10)
// ---------------------------------------------------------------------------
__global__ __launch_bounds__(256)
void wprep_kernel(const float* __restrict__ W)
{
    int id    = blockIdx.x * 256 + threadIdx.x;    // 0..163839
    int lane  = id & 31;
    int j     = (id >> 5) & 1;
    int natom = (id >> 6) & 31;
    int nbx   = (id >> 11) & 3;
    int kc    = id >> 13;                           // 0..19

    int n  = nbx * 256 + natom * 8 + (lane >> 2);
    int k0 = kc * 32 + j * 16 + (lane & 3) * 2;

    float w0 = W[(size_t)(k0 + 0) * VOCAB + n];
    float w1 = W[(size_t)(k0 + 1) * VOCAB + n];
    float w8 = W[(size_t)(k0 + 8) * VOCAB + n];
    float w9 = W[(size_t)(k0 + 9) * VOCAB + n];

    size_t blk  = (size_t)(kc * 4 + nbx) * 16384;
    size_t frag = (size_t)((natom * 2 + j) * 32 + lane) * 8;
    *(uint2*)(g_Wf + blk + frag) = make_uint2(pack_h(w0, w1), pack_h(w8, w9));
}

// ---------------------------------------------------------------------------
// Stage 3: fused joint GEMM, fp16 2-MMA split, 512 threads / 16 warps.
// Grid (4, 625). CTA tile 128x256; warp grid 4(M) x 4(N); warp tile 32x64
// (ma=2, na=8). BK=32, double buffer: [Ahi 8K | Alo 8K | B 16K] x 2.
// A producer: warp wid owns atom pi=wid>>1, k-sub j=wid&1 (halved vs R10).
// ---------------------------------------------------------------------------
#define BUF_BYTES 32768
#define SMEM_NEED 65536

__global__ __launch_bounds__(512, 1)
void joint_mma_kernel(const float* __restrict__ bout, float* __restrict__ out)
{
    extern __shared__ char smem[];

    const int t    = threadIdx.x;
    const int lane = t & 31;
    const int wid  = t >> 5;            // 0..15
    const int wy   = wid >> 2;          // 0..3  (M, 32 rows each)
    const int wx   = wid & 3;           // 0..3  (N, 64 cols each)
    const int g    = lane >> 2;
    const int tg   = lane & 3;
    const int m0   = blockIdx.y * 128;
    const int n0   = blockIdx.x * 256;
    const int bx   = blockIdx.x;

    // ---- A producer geometry: atom pi = wid>>1 (8 atoms), j = wid&1
    const int pi = wid >> 1;
    const int pj = wid & 1;
    const int r0 = m0 + pi * 16 + g;
    const int r1 = r0 + 8;
    const int bt0 = r0 / U_DIM, u0 = r0 - bt0 * U_DIM, bb0 = bt0 / T_DIM;
    const int bt1 = r1 / U_DIM, u1 = r1 - bt1 * U_DIM, bb1 = bt1 / T_DIM;
    const float* E0 = g_E + (size_t)bt0 * JOINT_DIM;
    const float* P0 = g_P + (size_t)(bb0 * U_DIM + u0) * JOINT_DIM;
    const float* E1 = g_E + (size_t)bt1 * JOINT_DIM;
    const float* P1 = g_P + (size_t)(bb1 * U_DIM + u1) * JOINT_DIM;
    const int kbase = pj * 16 + tg * 2;   // k offset within chunk (and +8)

    float acc[2][8][4];
#pragma unroll
    for (int ma = 0; ma < 2; ma++)
#pragma unroll
        for (int na = 0; na < 8; na++)
#pragma unroll
            for (int q = 0; q < 4; q++) acc[ma][na][q] = 0.f;

    auto prefetchA = [&](int kc, float2 (&e0)[2], float2 (&p0)[2],
                         float2 (&e1)[2], float2 (&p1)[2]) {
        const int off = kc * 32 + kbase;
        e0[0] = *(const float2*)(E0 + off);
        e0[1] = *(const float2*)(E0 + off + 8);
        p0[0] = *(const float2*)(P0 + off);
        p0[1] = *(const float2*)(P0 + off + 8);
        e1[0] = *(const float2*)(E1 + off);
        e1[1] = *(const float2*)(E1 + off + 8);
        p1[0] = *(const float2*)(P1 + off);
        p1[1] = *(const float2*)(P1 + off + 8);
    };
    auto storeA = [&](char* buf, const float2 (&e0)[2], const float2 (&p0)[2],
                      const float2 (&e1)[2], const float2 (&p1)[2]) {
        float x00 = tanh_fast(e0[0].x + p0[0].x);
        float x01 = tanh_fast(e0[0].y + p0[0].y);
        float x08 = tanh_fast(e0[1].x + p0[1].x);
        float x09 = tanh_fast(e0[1].y + p0[1].y);
        float x10 = tanh_fast(e1[0].x + p1[0].x);
        float x11 = tanh_fast(e1[0].y + p1[0].y);
        float x18 = tanh_fast(e1[1].x + p1[1].x);
        float x19 = tanh_fast(e1[1].y + p1[1].y);
        uint32_t a0 = pack_h(x00, x01);
        uint32_t a1 = pack_h(x10, x11);
        uint32_t a2 = pack_h(x08, x09);
        uint32_t a3 = pack_h(x18, x19);
        uint32_t b0 = pack_h_lo(x00, x01, a0);
        uint32_t b1 = pack_h_lo(x10, x11, a1);
        uint32_t b2 = pack_h_lo(x08, x09, a2);
        uint32_t b3 = pack_h_lo(x18, x19, a3);
        const int idx = (pi * 2 + pj) * 32 + lane;
        ((uint4*)buf)[idx]            = make_uint4(a0, a1, a2, a3);
        ((uint4*)(buf + 8192))[idx]   = make_uint4(b0, b1, b2, b3);
    };
    auto issueB = [&](int kc, char* buf) {
        const char* src = (const char*)g_Wf + (size_t)(kc * 4 + bx) * 16384
                        + (size_t)t * 32;
        uint32_t dst = smem_u32(buf + 16384 + t * 32);
        CP_ASYNC16(dst, src);
        CP_ASYNC16(dst + 16, src + 16);
    };

    // ---- prologue: fill buffer 0
    {
        issueB(0, smem);
        CP_COMMIT();
        float2 e0[2], p0[2], e1[2], p1[2];
        prefetchA(0, e0, p0, e1, p1);
        storeA(smem, e0, p0, e1, p1);
        CP_WAIT0();
    }
    __syncthreads();

#pragma unroll 1
    for (int kc = 0; kc < 20; kc++) {
        char* cbuf = smem + (kc & 1) * BUF_BYTES;
        char* nbuf = smem + ((kc + 1) & 1) * BUF_BYTES;
        const bool more = (kc < 19);

        float2 e0[2], p0[2], e1[2], p1[2];
        if (more) {
            issueB(kc + 1, nbuf);
            CP_COMMIT();
            prefetchA(kc + 1, e0, p0, e1, p1);
        }

        const uint4* Ah = (const uint4*)cbuf;
        const uint4* Al = (const uint4*)(cbuf + 8192);
        const uint2* Bf = (const uint2*)(cbuf + 16384);
#pragma unroll
        for (int j = 0; j < 2; j++) {
            uint2 bf[8];
#pragma unroll
            for (int na = 0; na < 8; na++)
                bf[na] = Bf[((wx * 8 + na) * 2 + j) * 32 + lane];
#pragma unroll
            for (int ma = 0; ma < 2; ma++) {
                const int aidx = ((wy * 2 + ma) * 2 + j) * 32 + lane;
                uint4 ah = Ah[aidx];
                uint4 al = Al[aidx];
#pragma unroll
                for (int na = 0; na < 8; na++) {
                    mma_f16(acc[ma][na], ah, bf[na]);   // hi * b
                    mma_f16(acc[ma][na], al, bf[na]);   // lo * b
                }
            }
        }

        if (more) {
            storeA(nbuf, e0, p0, e1, p1);
            CP_WAIT0();
        }
        __syncthreads();
    }

    // ---- epilogue: bias + streaming float2 stores
    float2 bias2[8];
#pragma unroll
    for (int na = 0; na < 8; na++)
        bias2[na] = *(const float2*)(bout + n0 + wx * 64 + na * 8 + tg * 2);

#pragma unroll
    for (int ma = 0; ma < 2; ma++) {
        const int ra = m0 + (wy * 2 + ma) * 16 + g;
        float* rowa = out + (size_t)ra * VOCAB + n0 + wx * 64;
        float* rowb = rowa + (size_t)8 * VOCAB;
#pragma unroll
        for (int na = 0; na < 8; na++) {
            float2 va, vb;
            va.x = acc[ma][na][0] + bias2[na].x;
            va.y = acc[ma][na][1] + bias2[na].y;
            vb.x = acc[ma][na][2] + bias2[na].x;
            vb.y = acc[ma][na][3] + bias2[na].y;
            __stcs((float2*)(rowa + na * 8 + tg * 2), va);
            __stcs((float2*)(rowb + na * 8 + tg * 2), vb);
        }
    }
}

// ---------------------------------------------------------------------------
// Launch. Inputs: 0 enc_out, 1 pred_out, 2 W_enc, 3 b_enc, 4 W_pred,
//                 5 W_out, 6 b_out.  Output fp32 [4,200,100,1024].
// ---------------------------------------------------------------------------
extern "C" void kernel_launch(void* const* d_in, const int* in_sizes, int n_in,
                              void* d_out, int out_size)
{
    const float* enc_out  = (const float*)d_in[0];
    const float* pred_out = (const float*)d_in[1];
    const float* W_enc    = (const float*)d_in[2];
    const float* b_enc    = (const float*)d_in[3];
    const float* W_pred   = (const float*)d_in[4];
    const float* W_out    = (const float*)d_in[5];
    const float* b_out    = (const float*)d_in[6];
    float* out = (float*)d_out;
    (void)in_sizes; (void)n_in; (void)out_size;

    cudaFuncSetAttribute(joint_mma_kernel,
                         cudaFuncAttributeMaxDynamicSharedMemorySize, SMEM_NEED);

    // Stage 2.5 first (independent of proj): W_out -> fp16 fragment stream.
    wprep_kernel<<<640, 256>>>(W_out);
    // Stage 1+2: both projections (z selects E vs P).
    {
        dim3 grid(JOINT_DIM / 64, (B_DIM * T_DIM + 63) / 64, 2);
        proj_kernel<<<grid, 256>>>(enc_out, pred_out, W_enc, W_pred, b_enc);
    }
    // Stage 3: tensor-core fused joint GEMM (512 threads, 16 warps).
    {
        dim3 grid(VOCAB / 256, (B_DIM * T_DIM * U_DIM) / 128);   // 4 x 625
        joint_mma_kernel<<<grid, 512, SMEM_NEED>>>(b_out, out);
    }
}

// round 12
// speedup vs baseline: 4.2596x; 1.4609x over previous
#include <cuda_runtime.h>
#include <cuda_fp16.h>
#include <cstdint>

// ===========================================================================
// TransducerJoint via mma.sync fp16 (HMMA):
//   logits[b,t,u,v] = tanh(E[bt,:] + P[b,u,:]) @ W_out + b_out
//   B=4 T=200 U=100 ENC=512 JOINT=640 VOCAB=1024;  M=80000, N=1024, K=640
//
// R12: R10/R11 pinned the kernel at the legacy-HMMA throughput ceiling
// (~14.5 cyc/HMMA/SMSP, warp count irrelevant). Halve the MMA count:
// single fp16 MMA (A fp16, B fp16, fp32 accum). Measured error model says
// +A-rounding ~2e-4 in quadrature with the 2.07e-4 measured -> ~2.9e-4.
// ===========================================================================

#define B_DIM 4
#define T_DIM 200
#define U_DIM 100
#define ENC_DIM 512
#define JOINT_DIM 640
#define VOCAB 1024

__device__ float g_E[B_DIM * T_DIM * JOINT_DIM];   // [800,640]
__device__ float g_P[B_DIM * U_DIM * JOINT_DIM];   // [400,640]
// W_out fp16 fragments: [20 kchunks][4 nblocks(256)] x 16KB
__device__ __align__(16) unsigned char g_Wf[20 * 4 * 16384];

// ---------------------------------------------------------------------------
// helpers
// ---------------------------------------------------------------------------
__device__ __forceinline__ uint32_t smem_u32(const void* p) {
    uint32_t a;
    asm("{ .reg .u64 t; cvta.to.shared.u64 t, %1; cvt.u32.u64 %0, t; }"
        : "=r"(a) : "l"(p));
    return a;
}
__device__ __forceinline__ float tanh_fast(float x) {
    float r; asm("tanh.approx.f32 %0, %1;" : "=f"(r) : "f"(x)); return r;
}
// pack two fp32 -> f16x2 (first arg -> LOW half = even-k element)
__device__ __forceinline__ uint32_t pack_h(float lo, float hi) {
    uint32_t r; asm("cvt.rn.f16x2.f32 %0, %1, %2;" : "=r"(r) : "f"(hi), "f"(lo));
    return r;
}
__device__ __forceinline__ void mma_f16(float* c, const uint4& a, const uint2& b) {
    asm volatile(
        "mma.sync.aligned.m16n8k16.row.col.f32.f16.f16.f32 "
        "{%0,%1,%2,%3}, {%4,%5,%6,%7}, {%8,%9}, {%0,%1,%2,%3};"
        : "+f"(c[0]), "+f"(c[1]), "+f"(c[2]), "+f"(c[3])
        : "r"(a.x), "r"(a.y), "r"(a.z), "r"(a.w), "r"(b.x), "r"(b.y));
}
#define CP_ASYNC16(dst, src) \
    asm volatile("cp.async.cg.shared.global [%0], [%1], 16;" \
                 :: "r"(dst), "l"(src) : "memory")
#define CP_COMMIT() asm volatile("cp.async.commit_group;" ::: "memory")
#define CP_WAIT0()  asm volatile("cp.async.wait_group 0;" ::: "memory")

// ---------------------------------------------------------------------------
// Stage 1+2 fused: z=0 -> E (M=800, +bias), z=1 -> P (M=400, no bias).
// 64x64x16 fp32 tiles (unchanged from the passing R9-R11 kernels).
// ---------------------------------------------------------------------------
__global__ __launch_bounds__(256)
void proj_kernel(const float* __restrict__ enc, const float* __restrict__ pred,
                 const float* __restrict__ W_enc, const float* __restrict__ W_pred,
                 const float* __restrict__ b_enc)
{
    const int z = blockIdx.z;
    const float* A    = z ? pred : enc;
    const float* W    = z ? W_pred : W_enc;
    const float* bias = z ? nullptr : b_enc;
    float* C          = z ? g_P : g_E;
    const int M       = z ? (B_DIM * U_DIM) : (B_DIM * T_DIM);

    const int BM = 64, BN = 64, BK = 16;
    const int m0 = blockIdx.y * BM;
    if (m0 >= M) return;
    const int n0 = blockIdx.x * BN;

    __shared__ float As[BK][BM];
    __shared__ float Bs[BK][BN];

    const int t  = threadIdx.x;
    const int tx = t & 15, ty = t >> 4;
    const int arow = t >> 2, ak = (t & 3) << 2;
    const int brow = t >> 4, bcol = (t & 15) << 2;

    float acc[4][4];
#pragma unroll
    for (int i = 0; i < 4; i++)
#pragma unroll
        for (int j = 0; j < 4; j++) acc[i][j] = 0.f;

    for (int k0 = 0; k0 < ENC_DIM; k0 += BK) {
        float4 av = make_float4(0.f, 0.f, 0.f, 0.f);
        if (m0 + arow < M)
            av = *(const float4*)(A + (size_t)(m0 + arow) * ENC_DIM + k0 + ak);
        As[ak + 0][arow] = av.x; As[ak + 1][arow] = av.y;
        As[ak + 2][arow] = av.z; As[ak + 3][arow] = av.w;
        *(float4*)&Bs[brow][bcol] =
            *(const float4*)(W + (size_t)(k0 + brow) * JOINT_DIM + n0 + bcol);
        __syncthreads();
#pragma unroll
        for (int k = 0; k < BK; k++) {
            float a[4], b[4];
#pragma unroll
            for (int i = 0; i < 4; i++) a[i] = As[k][ty * 4 + i];
#pragma unroll
            for (int j = 0; j < 4; j++) b[j] = Bs[k][tx * 4 + j];
#pragma unroll
            for (int i = 0; i < 4; i++)
#pragma unroll
                for (int j = 0; j < 4; j++)
                    acc[i][j] = fmaf(a[i], b[j], acc[i][j]);
        }
        __syncthreads();
    }
    float bv[4] = {0.f, 0.f, 0.f, 0.f};
    if (bias) {
        float4 b4 = *(const float4*)(bias + n0 + tx * 4);
        bv[0] = b4.x; bv[1] = b4.y; bv[2] = b4.z; bv[3] = b4.w;
    }
#pragma unroll
    for (int i = 0; i < 4; i++) {
        int row = m0 + ty * 4 + i;
        if (row < M) {
            float4 v;
            v.x = acc[i][0] + bv[0]; v.y = acc[i][1] + bv[1];
            v.z = acc[i][2] + bv[2]; v.w = acc[i][3] + bv[3];
            *(float4*)(C + (size_t)row * JOINT_DIM + n0 + tx * 4) = v;
        }
    }
}

// ---------------------------------------------------------------------------
// Stage 2.5: W_out[640,1024] -> single-fp16 mma.sync B-fragment layout.
// (unchanged from R10/R11)
// ---------------------------------------------------------------------------
__global__ __launch_bounds__(256)
void wprep_kernel(const float* __restrict__ W)
{
    int id    = blockIdx.x * 256 + threadIdx.x;    // 0..163839
    int lane  = id & 31;
    int j     = (id >> 5) & 1;
    int natom = (id >> 6) & 31;
    int nbx   = (id >> 11) & 3;
    int kc    = id >> 13;                           // 0..19

    int n  = nbx * 256 + natom * 8 + (lane >> 2);
    int k0 = kc * 32 + j * 16 + (lane & 3) * 2;

    float w0 = W[(size_t)(k0 + 0) * VOCAB + n];
    float w1 = W[(size_t)(k0 + 1) * VOCAB + n];
    float w8 = W[(size_t)(k0 + 8) * VOCAB + n];
    float w9 = W[(size_t)(k0 + 9) * VOCAB + n];

    size_t blk  = (size_t)(kc * 4 + nbx) * 16384;
    size_t frag = (size_t)((natom * 2 + j) * 32 + lane) * 8;
    *(uint2*)(g_Wf + blk + frag) = make_uint2(pack_h(w0, w1), pack_h(w8, w9));
}

// ---------------------------------------------------------------------------
// Stage 3: fused joint GEMM, SINGLE fp16 MMA, 512 threads / 16 warps.
// Grid (4, 625). CTA tile 128x256; warp grid 4(M) x 4(N); warp tile 32x64
// (ma=2, na=8). BK=32, double buffer: [A 8K | B 16K] x 2 = 48KB.
// A producer: warp wid owns atom pi=wid>>1, k-sub pj=wid&1.
// ---------------------------------------------------------------------------
#define BUF_BYTES 24576
#define SMEM_NEED 49152

__global__ __launch_bounds__(512, 1)
void joint_mma_kernel(const float* __restrict__ bout, float* __restrict__ out)
{
    extern __shared__ char smem[];

    const int t    = threadIdx.x;
    const int lane = t & 31;
    const int wid  = t >> 5;            // 0..15
    const int wy   = wid >> 2;          // 0..3  (M, 32 rows each)
    const int wx   = wid & 3;           // 0..3  (N, 64 cols each)
    const int g    = lane >> 2;
    const int tg   = lane & 3;
    const int m0   = blockIdx.y * 128;
    const int n0   = blockIdx.x * 256;
    const int bx   = blockIdx.x;

    // ---- A producer geometry: atom pi = wid>>1 (8 atoms), pj = wid&1
    const int pi = wid >> 1;
    const int pj = wid & 1;
    const int r0 = m0 + pi * 16 + g;
    const int r1 = r0 + 8;
    const int bt0 = r0 / U_DIM, u0 = r0 - bt0 * U_DIM, bb0 = bt0 / T_DIM;
    const int bt1 = r1 / U_DIM, u1 = r1 - bt1 * U_DIM, bb1 = bt1 / T_DIM;
    const float* E0 = g_E + (size_t)bt0 * JOINT_DIM;
    const float* P0 = g_P + (size_t)(bb0 * U_DIM + u0) * JOINT_DIM;
    const float* E1 = g_E + (size_t)bt1 * JOINT_DIM;
    const float* P1 = g_P + (size_t)(bb1 * U_DIM + u1) * JOINT_DIM;
    const int kbase = pj * 16 + tg * 2;   // k offset within chunk (and +8)

    float acc[2][8][4];
#pragma unroll
    for (int ma = 0; ma < 2; ma++)
#pragma unroll
        for (int na = 0; na < 8; na++)
#pragma unroll
            for (int q = 0; q < 4; q++) acc[ma][na][q] = 0.f;

    auto prefetchA = [&](int kc, float2 (&e0)[2], float2 (&p0)[2],
                         float2 (&e1)[2], float2 (&p1)[2]) {
        const int off = kc * 32 + kbase;
        e0[0] = *(const float2*)(E0 + off);
        e0[1] = *(const float2*)(E0 + off + 8);
        p0[0] = *(const float2*)(P0 + off);
        p0[1] = *(const float2*)(P0 + off + 8);
        e1[0] = *(const float2*)(E1 + off);
        e1[1] = *(const float2*)(E1 + off + 8);
        p1[0] = *(const float2*)(P1 + off);
        p1[1] = *(const float2*)(P1 + off + 8);
    };
    auto storeA = [&](char* buf, const float2 (&e0)[2], const float2 (&p0)[2],
                      const float2 (&e1)[2], const float2 (&p1)[2]) {
        float x00 = tanh_fast(e0[0].x + p0[0].x);
        float x01 = tanh_fast(e0[0].y + p0[0].y);
        float x08 = tanh_fast(e0[1].x + p0[1].x);
        float x09 = tanh_fast(e0[1].y + p0[1].y);
        float x10 = tanh_fast(e1[0].x + p1[0].x);
        float x11 = tanh_fast(e1[0].y + p1[0].y);
        float x18 = tanh_fast(e1[1].x + p1[1].x);
        float x19 = tanh_fast(e1[1].y + p1[1].y);
        const int idx = (pi * 2 + pj) * 32 + lane;
        ((uint4*)buf)[idx] = make_uint4(pack_h(x00, x01), pack_h(x10, x11),
                                        pack_h(x08, x09), pack_h(x18, x19));
    };
    auto issueB = [&](int kc, char* buf) {
        const char* src = (const char*)g_Wf + (size_t)(kc * 4 + bx) * 16384
                        + (size_t)t * 32;
        uint32_t dst = smem_u32(buf + 8192 + t * 32);
        CP_ASYNC16(dst, src);
        CP_ASYNC16(dst + 16, src + 16);
    };

    // ---- prologue: fill buffer 0
    {
        issueB(0, smem);
        CP_COMMIT();
        float2 e0[2], p0[2], e1[2], p1[2];
        prefetchA(0, e0, p0, e1, p1);
        storeA(smem, e0, p0, e1, p1);
        CP_WAIT0();
    }
    __syncthreads();

#pragma unroll 1
    for (int kc = 0; kc < 20; kc++) {
        char* cbuf = smem + (kc & 1) * BUF_BYTES;
        char* nbuf = smem + ((kc + 1) & 1) * BUF_BYTES;
        const bool more = (kc < 19);

        float2 e0[2], p0[2], e1[2], p1[2];
        if (more) {
            issueB(kc + 1, nbuf);
            CP_COMMIT();
            prefetchA(kc + 1, e0, p0, e1, p1);
        }

        const uint4* Ah = (const uint4*)cbuf;
        const uint2* Bf = (const uint2*)(cbuf + 8192);
#pragma unroll
        for (int j = 0; j < 2; j++) {
            uint2 bf[8];
#pragma unroll
            for (int na = 0; na < 8; na++)
                bf[na] = Bf[((wx * 8 + na) * 2 + j) * 32 + lane];
#pragma unroll
            for (int ma = 0; ma < 2; ma++) {
                const uint4 ah = Ah[((wy * 2 + ma) * 2 + j) * 32 + lane];
#pragma unroll
                for (int na = 0; na < 8; na++)
                    mma_f16(acc[ma][na], ah, bf[na]);
            }
        }

        if (more) {
            storeA(nbuf, e0, p0, e1, p1);
            CP_WAIT0();
        }
        __syncthreads();
    }

    // ---- epilogue: bias + streaming float2 stores
    float2 bias2[8];
#pragma unroll
    for (int na = 0; na < 8; na++)
        bias2[na] = *(const float2*)(bout + n0 + wx * 64 + na * 8 + tg * 2);

#pragma unroll
    for (int ma = 0; ma < 2; ma++) {
        const int ra = m0 + (wy * 2 + ma) * 16 + g;
        float* rowa = out + (size_t)ra * VOCAB + n0 + wx * 64;
        float* rowb = rowa + (size_t)8 * VOCAB;
#pragma unroll
        for (int na = 0; na < 8; na++) {
            float2 va, vb;
            va.x = acc[ma][na][0] + bias2[na].x;
            va.y = acc[ma][na][1] + bias2[na].y;
            vb.x = acc[ma][na][2] + bias2[na].x;
            vb.y = acc[ma][na][3] + bias2[na].y;
            __stcs((float2*)(rowa + na * 8 + tg * 2), va);
            __stcs((float2*)(rowb + na * 8 + tg * 2), vb);
        }
    }
}

// ---------------------------------------------------------------------------
// Launch. Inputs: 0 enc_out, 1 pred_out, 2 W_enc, 3 b_enc, 4 W_pred,
//                 5 W_out, 6 b_out.  Output fp32 [4,200,100,1024].
// ---------------------------------------------------------------------------
extern "C" void kernel_launch(void* const* d_in, const int* in_sizes, int n_in,
                              void* d_out, int out_size)
{
    const float* enc_out  = (const float*)d_in[0];
    const float* pred_out = (const float*)d_in[1];
    const float* W_enc    = (const float*)d_in[2];
    const float* b_enc    = (const float*)d_in[3];
    const float* W_pred   = (const float*)d_in[4];
    const float* W_out    = (const float*)d_in[5];
    const float* b_out    = (const float*)d_in[6];
    float* out = (float*)d_out;
    (void)in_sizes; (void)n_in; (void)out_size;

    cudaFuncSetAttribute(joint_mma_kernel,
                         cudaFuncAttributeMaxDynamicSharedMemorySize, SMEM_NEED);

    // Stage 2.5 first (independent of proj): W_out -> fp16 fragment stream.
    wprep_kernel<<<640, 256>>>(W_out);
    // Stage 1+2: both projections (z selects E vs P).
    {
        dim3 grid(JOINT_DIM / 64, (B_DIM * T_DIM + 63) / 64, 2);
        proj_kernel<<<grid, 256>>>(enc_out, pred_out, W_enc, W_pred, b_enc);
    }
    // Stage 3: tensor-core fused joint GEMM (single-MMA fp16).
    {
        dim3 grid(VOCAB / 256, (B_DIM * T_DIM * U_DIM) / 128);   // 4 x 625
        joint_mma_kernel<<<grid, 512, SMEM_NEED>>>(b_out, out);
    }
}

// round 13
// speedup vs baseline: 4.2762x; 1.0039x over previous
#include <cuda_runtime.h>
#include <cuda_fp16.h>
#include <cstdint>

// ===========================================================================
// TransducerJoint via mma.sync fp16 (HMMA):
//   logits[b,t,u,v] = tanh(E[bt,:] + P[b,u,:]) @ W_out + b_out
//   B=4 T=200 U=100 ENC=512 JOINT=640 VOCAB=1024;  M=80000, N=1024, K=640
//
// R13: R12 measurement shows ~1180 cyc fixed overhead per K-chunk next to
// ~1270 cyc of MMA issue. Halve the chunk count (BK 32 -> 64, 10 chunks),
// doubling MMA work per barrier. A-producer split into two halves woven
// between MMA j-phases to keep regs <= 128 at 512 threads. Numerics are
// bitwise identical to R12 (same MMA sequence per accumulator).
// ===========================================================================

#define B_DIM 4
#define T_DIM 200
#define U_DIM 100
#define ENC_DIM 512
#define JOINT_DIM 640
#define VOCAB 1024

__device__ float g_E[B_DIM * T_DIM * JOINT_DIM];   // [800,640]
__device__ float g_P[B_DIM * U_DIM * JOINT_DIM];   // [400,640]
// W_out fp16 fragments: [10 kchunks(64)][4 nblocks(256)] x 32KB
__device__ __align__(16) unsigned char g_Wf[10 * 4 * 32768];

// ---------------------------------------------------------------------------
// helpers
// ---------------------------------------------------------------------------
__device__ __forceinline__ uint32_t smem_u32(const void* p) {
    uint32_t a;
    asm("{ .reg .u64 t; cvta.to.shared.u64 t, %1; cvt.u32.u64 %0, t; }"
        : "=r"(a) : "l"(p));
    return a;
}
__device__ __forceinline__ float tanh_fast(float x) {
    float r; asm("tanh.approx.f32 %0, %1;" : "=f"(r) : "f"(x)); return r;
}
// pack two fp32 -> f16x2 (first arg -> LOW half = even-k element)
__device__ __forceinline__ uint32_t pack_h(float lo, float hi) {
    uint32_t r; asm("cvt.rn.f16x2.f32 %0, %1, %2;" : "=r"(r) : "f"(hi), "f"(lo));
    return r;
}
__device__ __forceinline__ void mma_f16(float* c, const uint4& a, const uint2& b) {
    asm volatile(
        "mma.sync.aligned.m16n8k16.row.col.f32.f16.f16.f32 "
        "{%0,%1,%2,%3}, {%4,%5,%6,%7}, {%8,%9}, {%0,%1,%2,%3};"
        : "+f"(c[0]), "+f"(c[1]), "+f"(c[2]), "+f"(c[3])
        : "r"(a.x), "r"(a.y), "r"(a.z), "r"(a.w), "r"(b.x), "r"(b.y));
}
#define CP_ASYNC16(dst, src) \
    asm volatile("cp.async.cg.shared.global [%0], [%1], 16;" \
                 :: "r"(dst), "l"(src) : "memory")
#define CP_COMMIT() asm volatile("cp.async.commit_group;" ::: "memory")
#define CP_WAIT0()  asm volatile("cp.async.wait_group 0;" ::: "memory")

// ---------------------------------------------------------------------------
// Stage 1+2 fused: z=0 -> E (M=800, +bias), z=1 -> P (M=400, no bias).
// 64x64x16 fp32 tiles (unchanged from the passing R9-R12 kernels).
// ---------------------------------------------------------------------------
__global__ __launch_bounds__(256)
void proj_kernel(const float* __restrict__ enc, const float* __restrict__ pred,
                 const float* __restrict__ W_enc, const float* __restrict__ W_pred,
                 const float* __restrict__ b_enc)
{
    const int z = blockIdx.z;
    const float* A    = z ? pred : enc;
    const float* W    = z ? W_pred : W_enc;
    const float* bias = z ? nullptr : b_enc;
    float* C          = z ? g_P : g_E;
    const int M       = z ? (B_DIM * U_DIM) : (B_DIM * T_DIM);

    const int BM = 64, BN = 64, BK = 16;
    const int m0 = blockIdx.y * BM;
    if (m0 >= M) return;
    const int n0 = blockIdx.x * BN;

    __shared__ float As[BK][BM];
    __shared__ float Bs[BK][BN];

    const int t  = threadIdx.x;
    const int tx = t & 15, ty = t >> 4;
    const int arow = t >> 2, ak = (t & 3) << 2;
    const int brow = t >> 4, bcol = (t & 15) << 2;

    float acc[4][4];
#pragma unroll
    for (int i = 0; i < 4; i++)
#pragma unroll
        for (int j = 0; j < 4; j++) acc[i][j] = 0.f;

    for (int k0 = 0; k0 < ENC_DIM; k0 += BK) {
        float4 av = make_float4(0.f, 0.f, 0.f, 0.f);
        if (m0 + arow < M)
            av = *(const float4*)(A + (size_t)(m0 + arow) * ENC_DIM + k0 + ak);
        As[ak + 0][arow] = av.x; As[ak + 1][arow] = av.y;
        As[ak + 2][arow] = av.z; As[ak + 3][arow] = av.w;
        *(float4*)&Bs[brow][bcol] =
            *(const float4*)(W + (size_t)(k0 + brow) * JOINT_DIM + n0 + bcol);
        __syncthreads();
#pragma unroll
        for (int k = 0; k < BK; k++) {
            float a[4], b[4];
#pragma unroll
            for (int i = 0; i < 4; i++) a[i] = As[k][ty * 4 + i];
#pragma unroll
            for (int j = 0; j < 4; j++) b[j] = Bs[k][tx * 4 + j];
#pragma unroll
            for (int i = 0; i < 4; i++)
#pragma unroll
                for (int j = 0; j < 4; j++)
                    acc[i][j] = fmaf(a[i], b[j], acc[i][j]);
        }
        __syncthreads();
    }
    float bv[4] = {0.f, 0.f, 0.f, 0.f};
    if (bias) {
        float4 b4 = *(const float4*)(bias + n0 + tx * 4);
        bv[0] = b4.x; bv[1] = b4.y; bv[2] = b4.z; bv[3] = b4.w;
    }
#pragma unroll
    for (int i = 0; i < 4; i++) {
        int row = m0 + ty * 4 + i;
        if (row < M) {
            float4 v;
            v.x = acc[i][0] + bv[0]; v.y = acc[i][1] + bv[1];
            v.z = acc[i][2] + bv[2]; v.w = acc[i][3] + bv[3];
            *(float4*)(C + (size_t)row * JOINT_DIM + n0 + tx * 4) = v;
        }
    }
}

// ---------------------------------------------------------------------------
// Stage 2.5: W_out[640,1024] -> fp16 mma.sync B-fragment layout, BK=64.
// One thread per (kc, nbx, natom, j, lane) = 163840.
//   n  = nbx*256 + natom*8 + (lane>>2)
//   k0 = kc*64 + j*16 + (lane&3)*2,  j = 0..3
//   frag uint2 {pack(W[k0][n],W[k0+1][n]), pack(W[k0+8][n],W[k0+9][n])}
//   at block (kc*4+nbx)*32KB, offset ((natom*4+j)*32+lane)*8.
// ---------------------------------------------------------------------------
__global__ __launch_bounds__(256)
void wprep_kernel(const float* __restrict__ W)
{
    int id    = blockIdx.x * 256 + threadIdx.x;    // 0..163839
    int lane  = id & 31;
    int j     = (id >> 5) & 3;
    int natom = (id >> 7) & 31;
    int nbx   = (id >> 12) & 3;
    int kc    = id >> 14;                           // 0..9

    int n  = nbx * 256 + natom * 8 + (lane >> 2);
    int k0 = kc * 64 + j * 16 + (lane & 3) * 2;

    float w0 = W[(size_t)(k0 + 0) * VOCAB + n];
    float w1 = W[(size_t)(k0 + 1) * VOCAB + n];
    float w8 = W[(size_t)(k0 + 8) * VOCAB + n];
    float w9 = W[(size_t)(k0 + 9) * VOCAB + n];

    size_t blk  = (size_t)(kc * 4 + nbx) * 32768;
    size_t frag = (size_t)((natom * 4 + j) * 32 + lane) * 8;
    *(uint2*)(g_Wf + blk + frag) = make_uint2(pack_h(w0, w1), pack_h(w8, w9));
}

// ---------------------------------------------------------------------------
// Stage 3: fused joint GEMM, single fp16 MMA, BK=64, 512 threads / 16 warps.
// Grid (4, 625). CTA tile 128x256; warp grid 4(M) x 4(N); warp tile 32x64.
// Double buffer: [A 16K | B 32K] x 2 = 96KB.
// A producer: warp wid -> atom pi=wid>>1, k-half group pj=wid&1 (32 k each),
// produced in two 16-k halves interleaved with the MMA j-phases.
// ---------------------------------------------------------------------------
#define BUF_BYTES 49152
#define SMEM_NEED 98304

__global__ __launch_bounds__(512, 1)
void joint_mma_kernel(const float* __restrict__ bout, float* __restrict__ out)
{
    extern __shared__ char smem[];

    const int t    = threadIdx.x;
    const int lane = t & 31;
    const int wid  = t >> 5;            // 0..15
    const int wy   = wid >> 2;          // 0..3  (M, 32 rows each)
    const int wx   = wid & 3;           // 0..3  (N, 64 cols each)
    const int g    = lane >> 2;
    const int tg   = lane & 3;
    const int m0   = blockIdx.y * 128;
    const int n0   = blockIdx.x * 256;
    const int bx   = blockIdx.x;

    // ---- A producer geometry: atom pi = wid>>1 (8 atoms), pj = wid&1
    const int pi = wid >> 1;
    const int pj = wid & 1;
    const int r0 = m0 + pi * 16 + g;
    const int r1 = r0 + 8;
    const int bt0 = r0 / U_DIM, u0 = r0 - bt0 * U_DIM, bb0 = bt0 / T_DIM;
    const int bt1 = r1 / U_DIM, u1 = r1 - bt1 * U_DIM, bb1 = bt1 / T_DIM;
    const float* E0 = g_E + (size_t)bt0 * JOINT_DIM;
    const float* P0 = g_P + (size_t)(bb0 * U_DIM + u0) * JOINT_DIM;
    const float* E1 = g_E + (size_t)bt1 * JOINT_DIM;
    const float* P1 = g_P + (size_t)(bb1 * U_DIM + u1) * JOINT_DIM;
    const int kbase = pj * 32 + tg * 2;   // + half*16 (+8) within chunk

    float acc[2][8][4];
#pragma unroll
    for (int ma = 0; ma < 2; ma++)
#pragma unroll
        for (int na = 0; na < 8; na++)
#pragma unroll
            for (int q = 0; q < 4; q++) acc[ma][na][q] = 0.f;

    // prefetch one 16-k half (8 LDG.64)
    auto prefA = [&](int kc, int half, float2 (&e0)[2], float2 (&p0)[2],
                     float2 (&e1)[2], float2 (&p1)[2]) {
        const int off = kc * 64 + kbase + half * 16;
        e0[0] = *(const float2*)(E0 + off);
        e0[1] = *(const float2*)(E0 + off + 8);
        p0[0] = *(const float2*)(P0 + off);
        p0[1] = *(const float2*)(P0 + off + 8);
        e1[0] = *(const float2*)(E1 + off);
        e1[1] = *(const float2*)(E1 + off + 8);
        p1[0] = *(const float2*)(P1 + off);
        p1[1] = *(const float2*)(P1 + off + 8);
    };
    // convert + store one fragment (j = pj*2 + half)
    auto storeAh = [&](char* buf, int half, const float2 (&e0)[2],
                       const float2 (&p0)[2], const float2 (&e1)[2],
                       const float2 (&p1)[2]) {
        float x00 = tanh_fast(e0[0].x + p0[0].x);
        float x01 = tanh_fast(e0[0].y + p0[0].y);
        float x08 = tanh_fast(e0[1].x + p0[1].x);
        float x09 = tanh_fast(e0[1].y + p0[1].y);
        float x10 = tanh_fast(e1[0].x + p1[0].x);
        float x11 = tanh_fast(e1[0].y + p1[0].y);
        float x18 = tanh_fast(e1[1].x + p1[1].x);
        float x19 = tanh_fast(e1[1].y + p1[1].y);
        const int idx = (pi * 4 + pj * 2 + half) * 32 + lane;
        ((uint4*)buf)[idx] = make_uint4(pack_h(x00, x01), pack_h(x10, x11),
                                        pack_h(x08, x09), pack_h(x18, x19));
    };
    auto issueB = [&](int kc, char* buf) {
        const char* src = (const char*)g_Wf + (size_t)(kc * 4 + bx) * 32768
                        + (size_t)t * 64;
        uint32_t dst = smem_u32(buf + 16384 + t * 64);
#pragma unroll
        for (int i = 0; i < 4; i++)
            CP_ASYNC16(dst + i * 16, src + i * 16);
    };

    // ---- prologue: fill buffer 0
    {
        issueB(0, smem);
        CP_COMMIT();
        float2 e0[2], p0[2], e1[2], p1[2];
        prefA(0, 0, e0, p0, e1, p1);
        storeAh(smem, 0, e0, p0, e1, p1);
        prefA(0, 1, e0, p0, e1, p1);
        storeAh(smem, 1, e0, p0, e1, p1);
        CP_WAIT0();
    }
    __syncthreads();

#pragma unroll 1
    for (int kc = 0; kc < 10; kc++) {
        char* cbuf = smem + (kc & 1) * BUF_BYTES;
        char* nbuf = smem + ((kc + 1) & 1) * BUF_BYTES;
        const bool more = (kc < 9);

        const uint4* Ah = (const uint4*)cbuf;
        const uint2* Bf = (const uint2*)(cbuf + 16384);

        float2 e0[2], p0[2], e1[2], p1[2];
        if (more) {
            issueB(kc + 1, nbuf);
            CP_COMMIT();
            prefA(kc + 1, 0, e0, p0, e1, p1);
        }

        // ---- MMA phase j = 0,1
#pragma unroll
        for (int j = 0; j < 2; j++) {
            uint2 bf[8];
#pragma unroll
            for (int na = 0; na < 8; na++)
                bf[na] = Bf[((wx * 8 + na) * 4 + j) * 32 + lane];
#pragma unroll
            for (int ma = 0; ma < 2; ma++) {
                const uint4 ah = Ah[((wy * 2 + ma) * 4 + j) * 32 + lane];
#pragma unroll
                for (int na = 0; na < 8; na++)
                    mma_f16(acc[ma][na], ah, bf[na]);
            }
        }

        if (more) {
            storeAh(nbuf, 0, e0, p0, e1, p1);
            prefA(kc + 1, 1, e0, p0, e1, p1);
        }

        // ---- MMA phase j = 2,3
#pragma unroll
        for (int j = 2; j < 4; j++) {
            uint2 bf[8];
#pragma unroll
            for (int na = 0; na < 8; na++)
                bf[na] = Bf[((wx * 8 + na) * 4 + j) * 32 + lane];
#pragma unroll
            for (int ma = 0; ma < 2; ma++) {
                const uint4 ah = Ah[((wy * 2 + ma) * 4 + j) * 32 + lane];
#pragma unroll
                for (int na = 0; na < 8; na++)
                    mma_f16(acc[ma][na], ah, bf[na]);
            }
        }

        if (more) {
            storeAh(nbuf, 1, e0, p0, e1, p1);
            CP_WAIT0();
        }
        __syncthreads();
    }

    // ---- epilogue: bias + streaming float2 stores
    float2 bias2[8];
#pragma unroll
    for (int na = 0; na < 8; na++)
        bias2[na] = *(const float2*)(bout + n0 + wx * 64 + na * 8 + tg * 2);

#pragma unroll
    for (int ma = 0; ma < 2; ma++) {
        const int ra = m0 + (wy * 2 + ma) * 16 + g;
        float* rowa = out + (size_t)ra * VOCAB + n0 + wx * 64;
        float* rowb = rowa + (size_t)8 * VOCAB;
#pragma unroll
        for (int na = 0; na < 8; na++) {
            float2 va, vb;
            va.x = acc[ma][na][0] + bias2[na].x;
            va.y = acc[ma][na][1] + bias2[na].y;
            vb.x = acc[ma][na][2] + bias2[na].x;
            vb.y = acc[ma][na][3] + bias2[na].y;
            __stcs((float2*)(rowa + na * 8 + tg * 2), va);
            __stcs((float2*)(rowb + na * 8 + tg * 2), vb);
        }
    }
}

// ---------------------------------------------------------------------------
// Launch. Inputs: 0 enc_out, 1 pred_out, 2 W_enc, 3 b_enc, 4 W_pred,
//                 5 W_out, 6 b_out.  Output fp32 [4,200,100,1024].
// ---------------------------------------------------------------------------
extern "C" void kernel_launch(void* const* d_in, const int* in_sizes, int n_in,
                              void* d_out, int out_size)
{
    const float* enc_out  = (const float*)d_in[0];
    const float* pred_out = (const float*)d_in[1];
    const float* W_enc    = (const float*)d_in[2];
    const float* b_enc    = (const float*)d_in[3];
    const float* W_pred   = (const float*)d_in[4];
    const float* W_out    = (const float*)d_in[5];
    const float* b_out    = (const float*)d_in[6];
    float* out = (float*)d_out;
    (void)in_sizes; (void)n_in; (void)out_size;

    cudaFuncSetAttribute(joint_mma_kernel,
                         cudaFuncAttributeMaxDynamicSharedMemorySize, SMEM_NEED);

    // Stage 2.5 first (independent of proj): W_out -> fp16 fragment stream.
    wprep_kernel<<<640, 256>>>(W_out);
    // Stage 1+2: both projections (z selects E vs P).
    {
        dim3 grid(JOINT_DIM / 64, (B_DIM * T_DIM + 63) / 64, 2);
        proj_kernel<<<grid, 256>>>(enc_out, pred_out, W_enc, W_pred, b_enc);
    }
    // Stage 3: tensor-core fused joint GEMM (BK=64, 10 chunks).
    {
        dim3 grid(VOCAB / 256, (B_DIM * T_DIM * U_DIM) / 128);   // 4 x 625
        joint_mma_kernel<<<grid, 512, SMEM_NEED>>>(b_out, out);
    }
}